// round 15
// baseline (speedup 1.0000x reference)
#include <cuda_runtime.h>
#include <cuda_bf16.h>
#include <math.h>

// Problem constants
#define BATCH 256
#define Hh 26
#define Ww 26
#define HW (Hh * Ww)          // 676
#define A_NUM 5
#define NCLS 20
#define CPA 25                 // channels per anchor (20 cls, conf, xy, wh)
#define CH (A_NUM * CPA)       // 125
#define TOTAL (BATCH * HW)     // 173056 = 676 * 256 exactly
#define NBLOCKS 676            // all blocks working; dummies removed

__device__ __constant__ float c_aw[5] = {1.3221f, 3.19275f, 5.05587f, 9.47112f, 11.2364f};
__device__ __constant__ float c_ah[5] = {1.73145f, 4.00944f, 8.09892f, 4.84053f, 10.0071f};

// cross-launch state: g_acc / g_done are zeroed by the last block of every
// launch, so each replay starts clean (stream-ordering guarantees this
// happens-before the next launch's atomics). Static init covers launch #1.
__device__ float g_acc[4] = {0.f, 0.f, 0.f, 0.f};
__device__ unsigned int g_done = 0;

// sigmoid via single MUFU.TANH (validated ~1e-6 at output; champion body)
__device__ __forceinline__ float fsigmoid(float x) {
    return fmaf(0.5f, __tanhf(0.5f * x), 0.5f);
}

__global__ void __launch_bounds__(256, 5) yolo_loss_kernel(
    const float* __restrict__ pred,   // (B, 125, 26, 26)
    const float* __restrict__ tgt,    // (B, 26, 26, 25)
    float* __restrict__ out)          // 4 floats: box, conf, noobj, cls
{
    int i = blockIdx.x * 256 + threadIdx.x;   // always < TOTAL (grid exact)

    float box_l = 0.f, conf_l = 0.f, noobj_l = 0.f, cls_l = 0.f;

    {
        int b = i / HW;
        int hw = i - b * HW;
        const float* __restrict__ pbase = pred + (size_t)b * CH * HW + hw;
        const float* __restrict__ t = tgt + (size_t)i * CPA;

        // front-batch all 25 pred plane loads (coalesced, 1 line each)
        float p[A_NUM * 5];
        #pragma unroll
        for (int a = 0; a < A_NUM; a++) {
            #pragma unroll
            for (int j = 0; j < 5; j++) {
                p[a * 5 + j] = __ldg(&pbase[(a * CPA + 20 + j) * HW]);
            }
        }

        float gconf = __ldg(&t[20]);
        float gx = __ldg(&t[21]), gy = __ldg(&t[22]);
        float gw = __ldg(&t[23]), gh = __ldg(&t[24]);

        float gx1 = gx - 0.5f * gw, gy1 = gy - 0.5f * gh;
        float gx2 = gx + 0.5f * gw, gy2 = gy + 0.5f * gh;
        float garea = gw * gh;

        // division-free argmax, deferred conf sigmoid
        float bI = 0.f, bU = 1.f;
        int   best_a = 0;
        float bpx = 0.f, bpy = 0.f, bpw = 0.f, bph = 0.f, btc = 0.f;

        #pragma unroll
        for (int a = 0; a < A_NUM; a++) {
            float tc = p[a * 5 + 0];
            float px = fsigmoid(p[a * 5 + 1]);
            float py = fsigmoid(p[a * 5 + 2]);
            float pw = __expf(p[a * 5 + 3]) * c_aw[a];
            float ph = __expf(p[a * 5 + 4]) * c_ah[a];

            float ax1 = px - 0.5f * pw, ay1 = py - 0.5f * ph;
            float ax2 = px + 0.5f * pw, ay2 = py + 0.5f * ph;
            float iw = fmaxf(fminf(ax2, gx2) - fmaxf(ax1, gx1), 0.0f);
            float ih = fmaxf(fminf(ay2, gy2) - fmaxf(ay1, gy1), 0.0f);
            float inter = iw * ih;
            float uni = pw * ph + garea - inter + 1e-10f;   // > 0

            bool better = (a == 0) || (inter * bU > bI * uni);
            if (better) {
                bI = inter; bU = uni;
                best_a = a;
                bpx = px; bpy = py; bpw = pw; bph = ph; btc = tc;
            }
        }

        float bconf = fsigmoid(btc);

        bool obj = (gconf != 0.0f);
        if (obj) {
            float dx = bpx - gx, dy = bpy - gy, dw = bpw - gw, dh = bph - gh;
            box_l  = dx * dx + dy * dy + dw * dw + dh * dh;
            float dc = bconf - gconf;
            conf_l = dc * dc;

            const float* __restrict__ lb = pbase + (size_t)(best_a * CPA) * HW;
            float logits[NCLS];
            float m = -INFINITY;
            #pragma unroll
            for (int c = 0; c < NCLS; c++) {
                float v = __ldg(&lb[c * HW]);
                logits[c] = v;
                m = fmaxf(m, v);
            }
            float s = 0.f;
            #pragma unroll
            for (int c = 0; c < NCLS; c++) s += __expf(logits[c] - m);
            float lse = m + __logf(s);

            int label = 0;
            float bestv = __ldg(&t[0]);
            #pragma unroll
            for (int c = 1; c < NCLS; c++) {
                float v = __ldg(&t[c]);
                if (v > bestv) { bestv = v; label = c; }
            }
            cls_l = lse - logits[label];
        } else {
            noobj_l = bconf * bconf;
        }
    }

    // ---- block reduction of 4 partials
    #pragma unroll
    for (int off = 16; off > 0; off >>= 1) {
        box_l   += __shfl_down_sync(0xFFFFFFFFu, box_l,   off);
        conf_l  += __shfl_down_sync(0xFFFFFFFFu, conf_l,  off);
        noobj_l += __shfl_down_sync(0xFFFFFFFFu, noobj_l, off);
        cls_l   += __shfl_down_sync(0xFFFFFFFFu, cls_l,   off);
    }

    __shared__ float sm[4][8];
    __shared__ bool s_last;
    int lane = threadIdx.x & 31;
    int wid  = threadIdx.x >> 5;
    if (lane == 0) {
        sm[0][wid] = box_l;
        sm[1][wid] = conf_l;
        sm[2][wid] = noobj_l;
        sm[3][wid] = cls_l;
    }
    __syncthreads();
    if (threadIdx.x == 0) {
        float v0 = 0.f, v1 = 0.f, v2 = 0.f, v3 = 0.f;
        #pragma unroll
        for (int w = 0; w < 8; w++) {
            v0 += sm[0][w]; v1 += sm[1][w]; v2 += sm[2][w]; v3 += sm[3][w];
        }
        // fire-and-forget global adds (4 distinct addresses, no contention)
        atomicAdd(&g_acc[0], v0);
        atomicAdd(&g_acc[1], v1);
        atomicAdd(&g_acc[2], v2);
        atomicAdd(&g_acc[3], v3);
        __threadfence();
        unsigned int done = atomicAdd(&g_done, 1u);
        s_last = (done == NBLOCKS - 1);
    }
    __syncthreads();

    // ---- last arriving block: scale + store + reset state for next replay
    if (s_last && threadIdx.x == 0) {
        __threadfence();                  // all adds visible
        const float inv_b = 1.0f / (float)BATCH;
        out[0] = g_acc[0] * (5.0f * inv_b);   // LAMBDA_COORD
        out[1] = g_acc[1] * (1.0f * inv_b);   // LAMBDA_OBJ
        out[2] = g_acc[2] * (0.5f * inv_b);   // LAMBDA_NOOBJ
        out[3] = g_acc[3] * (1.0f * inv_b);   // LAMBDA_CLS
        g_acc[0] = 0.f; g_acc[1] = 0.f; g_acc[2] = 0.f; g_acc[3] = 0.f;
        g_done = 0;                       // clean state for next replay
        __threadfence();
    }
}

extern "C" void kernel_launch(void* const* d_in, const int* in_sizes, int n_in,
                              void* d_out, int out_size) {
    const float* pred = (const float*)d_in[0];
    const float* tgt  = (const float*)d_in[1];
    float* out = (float*)d_out;

    yolo_loss_kernel<<<NBLOCKS, 256>>>(pred, tgt, out);   // single graph node
}

// round 16
// speedup vs baseline: 1.1250x; 1.1250x over previous
#include <cuda_runtime.h>
#include <cuda_bf16.h>
#include <math.h>

// Problem constants
#define BATCH 256
#define Hh 26
#define Ww 26
#define HW (Hh * Ww)          // 676
#define A_NUM 5
#define NCLS 20
#define CPA 25                 // channels per anchor (20 cls, conf, xy, wh)
#define CH (A_NUM * CPA)       // 125
#define TOTAL (BATCH * HW)     // 173056 = 676 * 256 exactly
#define NBLOCKS 740            // 5 * 148 SMs — balanced wave

__device__ __constant__ float c_aw[5] = {1.3221f, 3.19275f, 5.05587f, 9.47112f, 11.2364f};
__device__ __constant__ float c_ah[5] = {1.73145f, 4.00944f, 8.09892f, 4.84053f, 10.0071f};

// cross-launch state: partials are fully overwritten each launch (no zeroing);
// g_done is reset to 0 by the last block each launch (clean for next replay).
__device__ float4 g_part[NBLOCKS];
__device__ unsigned int g_done = 0;

// sigmoid via single MUFU.TANH (validated ~1e-6 at output)
__device__ __forceinline__ float fsigmoid(float x) {
    return fmaf(0.5f, __tanhf(0.5f * x), 0.5f);
}

__global__ void __launch_bounds__(256, 5) yolo_loss_kernel(
    const float* __restrict__ pred,   // (B, 125, 26, 26)
    const float* __restrict__ tgt,    // (B, 26, 26, 25)
    float* __restrict__ out)          // 4 floats: box, conf, noobj, cls
{
    int i = blockIdx.x * 256 + threadIdx.x;

    float box_l = 0.f, conf_l = 0.f, noobj_l = 0.f, cls_l = 0.f;

    if (i < TOTAL) {
        int b = i / HW;
        int hw = i - b * HW;
        const float* __restrict__ pbase = pred + (size_t)b * CH * HW + hw;
        const float* __restrict__ t = tgt + (size_t)i * CPA;

        // front-batch all 25 pred plane loads (coalesced, 1 line each)
        float p[A_NUM * 5];
        #pragma unroll
        for (int a = 0; a < A_NUM; a++) {
            #pragma unroll
            for (int j = 0; j < 5; j++) {
                p[a * 5 + j] = __ldg(&pbase[(a * CPA + 20 + j) * HW]);
            }
        }

        float gconf = __ldg(&t[20]);
        float gx = __ldg(&t[21]), gy = __ldg(&t[22]);
        float gw = __ldg(&t[23]), gh = __ldg(&t[24]);

        float gx1 = gx - 0.5f * gw, gy1 = gy - 0.5f * gh;
        float gx2 = gx + 0.5f * gw, gy2 = gy + 0.5f * gh;
        float garea = gw * gh;

        // division-free argmax, deferred conf sigmoid
        float bI = 0.f, bU = 1.f;
        int   best_a = 0;
        float bpx = 0.f, bpy = 0.f, bpw = 0.f, bph = 0.f, btc = 0.f;

        #pragma unroll
        for (int a = 0; a < A_NUM; a++) {
            float tc = p[a * 5 + 0];
            float px = fsigmoid(p[a * 5 + 1]);
            float py = fsigmoid(p[a * 5 + 2]);
            float pw = __expf(p[a * 5 + 3]) * c_aw[a];
            float ph = __expf(p[a * 5 + 4]) * c_ah[a];

            float ax1 = px - 0.5f * pw, ay1 = py - 0.5f * ph;
            float ax2 = px + 0.5f * pw, ay2 = py + 0.5f * ph;
            float iw = fmaxf(fminf(ax2, gx2) - fmaxf(ax1, gx1), 0.0f);
            float ih = fmaxf(fminf(ay2, gy2) - fmaxf(ay1, gy1), 0.0f);
            float inter = iw * ih;
            float uni = pw * ph + garea - inter + 1e-10f;   // > 0

            bool better = (a == 0) || (inter * bU > bI * uni);
            if (better) {
                bI = inter; bU = uni;
                best_a = a;
                bpx = px; bpy = py; bpw = pw; bph = ph; btc = tc;
            }
        }

        float bconf = fsigmoid(btc);

        bool obj = (gconf != 0.0f);
        if (obj) {
            float dx = bpx - gx, dy = bpy - gy, dw = bpw - gw, dh = bph - gh;
            box_l  = dx * dx + dy * dy + dw * dw + dh * dh;
            float dc = bconf - gconf;
            conf_l = dc * dc;

            const float* __restrict__ lb = pbase + (size_t)(best_a * CPA) * HW;
            float logits[NCLS];
            float m = -INFINITY;
            #pragma unroll
            for (int c = 0; c < NCLS; c++) {
                float v = __ldg(&lb[c * HW]);
                logits[c] = v;
                m = fmaxf(m, v);
            }
            float s = 0.f;
            #pragma unroll
            for (int c = 0; c < NCLS; c++) s += __expf(logits[c] - m);
            float lse = m + __logf(s);

            int label = 0;
            float bestv = __ldg(&t[0]);
            #pragma unroll
            for (int c = 1; c < NCLS; c++) {
                float v = __ldg(&t[c]);
                if (v > bestv) { bestv = v; label = c; }
            }
            cls_l = lse - logits[label];
        } else {
            noobj_l = bconf * bconf;
        }
    }

    // ---- block reduction of 4 partials
    #pragma unroll
    for (int off = 16; off > 0; off >>= 1) {
        box_l   += __shfl_down_sync(0xFFFFFFFFu, box_l,   off);
        conf_l  += __shfl_down_sync(0xFFFFFFFFu, conf_l,  off);
        noobj_l += __shfl_down_sync(0xFFFFFFFFu, noobj_l, off);
        cls_l   += __shfl_down_sync(0xFFFFFFFFu, cls_l,   off);
    }

    __shared__ float sm[4][8];
    __shared__ bool s_last;
    int lane = threadIdx.x & 31;
    int wid  = threadIdx.x >> 5;
    if (lane == 0) {
        sm[0][wid] = box_l;
        sm[1][wid] = conf_l;
        sm[2][wid] = noobj_l;
        sm[3][wid] = cls_l;
    }
    __syncthreads();
    if (threadIdx.x == 0) {
        float v0 = 0.f, v1 = 0.f, v2 = 0.f, v3 = 0.f;
        #pragma unroll
        for (int w = 0; w < 8; w++) {
            v0 += sm[0][w]; v1 += sm[1][w]; v2 += sm[2][w]; v3 += sm[3][w];
        }
        g_part[blockIdx.x] = make_float4(v0, v1, v2, v3);
        __threadfence();
        unsigned int done = atomicAdd(&g_done, 1u);
        s_last = (done == NBLOCKS - 1);
    }
    __syncthreads();

    // ---- last arriving block: final reduction, direct store, reset counter
    if (s_last) {
        float v0 = 0.f, v1 = 0.f, v2 = 0.f, v3 = 0.f;
        for (int k = threadIdx.x; k < NBLOCKS; k += 256) {
            float4 pp = g_part[k];
            v0 += pp.x; v1 += pp.y; v2 += pp.z; v3 += pp.w;
        }
        #pragma unroll
        for (int off = 16; off > 0; off >>= 1) {
            v0 += __shfl_down_sync(0xFFFFFFFFu, v0, off);
            v1 += __shfl_down_sync(0xFFFFFFFFu, v1, off);
            v2 += __shfl_down_sync(0xFFFFFFFFu, v2, off);
            v3 += __shfl_down_sync(0xFFFFFFFFu, v3, off);
        }
        __syncthreads();   // sm reuse safe
        if (lane == 0) {
            sm[0][wid] = v0; sm[1][wid] = v1; sm[2][wid] = v2; sm[3][wid] = v3;
        }
        __syncthreads();
        if (threadIdx.x == 0) {
            float r0 = 0.f, r1 = 0.f, r2 = 0.f, r3 = 0.f;
            #pragma unroll
            for (int w = 0; w < 8; w++) {
                r0 += sm[0][w]; r1 += sm[1][w]; r2 += sm[2][w]; r3 += sm[3][w];
            }
            const float inv_b = 1.0f / (float)BATCH;
            out[0] = r0 * (5.0f * inv_b);   // LAMBDA_COORD
            out[1] = r1 * (1.0f * inv_b);   // LAMBDA_OBJ
            out[2] = r2 * (0.5f * inv_b);   // LAMBDA_NOOBJ
            out[3] = r3 * (1.0f * inv_b);   // LAMBDA_CLS
            g_done = 0;                     // clean state for next replay
            __threadfence();
        }
    }
}

extern "C" void kernel_launch(void* const* d_in, const int* in_sizes, int n_in,
                              void* d_out, int out_size) {
    const float* pred = (const float*)d_in[0];
    const float* tgt  = (const float*)d_in[1];
    float* out = (float*)d_out;

    yolo_loss_kernel<<<NBLOCKS, 256>>>(pred, tgt, out);   // single graph node
}

// round 17
// speedup vs baseline: 1.1278x; 1.0025x over previous
#include <cuda_runtime.h>
#include <cuda_bf16.h>
#include <math.h>

// Problem constants
#define BATCH 256
#define Hh 26
#define Ww 26
#define HW (Hh * Ww)          // 676
#define A_NUM 5
#define NCLS 20
#define CPA 25                 // floats per cell (20 cls, conf, xy, wh)
#define CH (A_NUM * CPA)       // 125
#define TOTAL (BATCH * HW)     // 173056 = 676 * 256 exactly
#define CPB 256                // cells per block
#define NBLOCKS 740            // 5 * 148 SMs — balanced wave (blocks >= 676 idle)

__device__ __constant__ float c_aw[5] = {1.3221f, 3.19275f, 5.05587f, 9.47112f, 11.2364f};
__device__ __constant__ float c_ah[5] = {1.73145f, 4.00944f, 8.09892f, 4.84053f, 10.0071f};

// cross-launch state: partials fully overwritten each launch; g_done reset by last block.
__device__ float4 g_part[NBLOCKS];
__device__ unsigned int g_done = 0;

// sigmoid via single MUFU.TANH (validated ~1e-6 at output)
__device__ __forceinline__ float fsigmoid(float x) {
    return fmaf(0.5f, __tanhf(0.5f * x), 0.5f);
}

__global__ void __launch_bounds__(256, 5) yolo_loss_kernel(
    const float* __restrict__ pred,   // (B, 125, 26, 26)
    const float* __restrict__ tgt,    // (B, 26, 26, 25)
    float* __restrict__ out)          // 4 floats: box, conf, noobj, cls
{
    __shared__ float st[CPB * CPA];   // staged target slab (25600 B, coalesced fill)
    __shared__ int s_list[CPB];       // obj worklist: local_cell | (best_a << 8)
    __shared__ int s_cnt;
    __shared__ float sm[4][8];
    __shared__ bool s_last;

    if (threadIdx.x == 0) s_cnt = 0;

    int base = blockIdx.x * CPB;
    bool working = (base < TOTAL);    // uniform per block

    // ---- stage target slab: float4 coalesced (kills 8x sector amplification)
    if (working) {
        const float4* __restrict__ src = (const float4*)(tgt + (size_t)base * CPA);
        float4* dst = (float4*)st;
        #pragma unroll
        for (int k = threadIdx.x; k < CPB * CPA / 4; k += 256)
            dst[k] = __ldg(&src[k]);
    }
    __syncthreads();

    float box_l = 0.f, conf_l = 0.f, noobj_l = 0.f, cls_l = 0.f;

    if (working) {
        int i = base + threadIdx.x;
        int b = i / HW;
        int hw = i - b * HW;
        const float* __restrict__ pbase = pred + (size_t)b * CH * HW + hw;
        const float* t = st + threadIdx.x * CPA;   // conflict-free (25 coprime 32)

        // front-batch all 25 pred plane loads (coalesced, 1-2 lines each)
        float p[A_NUM * 5];
        #pragma unroll
        for (int a = 0; a < A_NUM; a++) {
            #pragma unroll
            for (int j = 0; j < 5; j++) {
                p[a * 5 + j] = __ldg(&pbase[(a * CPA + 20 + j) * HW]);
            }
        }

        float gconf = t[20];
        float gx = t[21], gy = t[22], gw = t[23], gh = t[24];

        float gx1 = gx - 0.5f * gw, gy1 = gy - 0.5f * gh;
        float gx2 = gx + 0.5f * gw, gy2 = gy + 0.5f * gh;
        float garea = gw * gh;

        // division-free argmax, deferred conf sigmoid
        float bI = 0.f, bU = 1.f;
        int   best_a = 0;
        float bpx = 0.f, bpy = 0.f, bpw = 0.f, bph = 0.f, btc = 0.f;

        #pragma unroll
        for (int a = 0; a < A_NUM; a++) {
            float tc = p[a * 5 + 0];
            float px = fsigmoid(p[a * 5 + 1]);
            float py = fsigmoid(p[a * 5 + 2]);
            float pw = __expf(p[a * 5 + 3]) * c_aw[a];
            float ph = __expf(p[a * 5 + 4]) * c_ah[a];

            float ax1 = px - 0.5f * pw, ay1 = py - 0.5f * ph;
            float ax2 = px + 0.5f * pw, ay2 = py + 0.5f * ph;
            float iw = fmaxf(fminf(ax2, gx2) - fmaxf(ax1, gx1), 0.0f);
            float ih = fmaxf(fminf(ay2, gy2) - fmaxf(ay1, gy1), 0.0f);
            float inter = iw * ih;
            float uni = pw * ph + garea - inter + 1e-10f;   // > 0

            bool better = (a == 0) || (inter * bU > bI * uni);
            if (better) {
                bI = inter; bU = uni;
                best_a = a;
                bpx = px; bpy = py; bpw = pw; bph = ph; btc = tc;
            }
        }

        float bconf = fsigmoid(btc);

        bool obj = (gconf != 0.0f);
        if (obj) {
            float dx = bpx - gx, dy = bpy - gy, dw = bpw - gw, dh = bph - gh;
            box_l  = dx * dx + dy * dy + dw * dw + dh * dh;
            float dc = bconf - gconf;
            conf_l = dc * dc;
            int slot = atomicAdd(&s_cnt, 1);    // cls loss deferred to drain phase
            s_list[slot] = threadIdx.x | (best_a << 8);
        } else {
            noobj_l = bconf * bconf;
        }
    }

    __syncthreads();

    // ---- drain: one warp per obj cell, lanes parallel over the 20 classes.
    // Replaces 20 serial scattered LDGs + logits[20] regs per obj thread with
    // one parallel LDG per cell; one-hot comes from the staged smem slab.
    int lane = threadIdx.x & 31;
    int wid  = threadIdx.x >> 5;
    int cnt = s_cnt;

    for (int k = wid; k < cnt; k += 8) {
        int e = s_list[k];
        int local = e & 0xFF;
        int a     = e >> 8;
        int ci = base + local;
        int b  = ci / HW;
        int hw = ci - b * HW;
        const float* __restrict__ lb = pred + (size_t)b * CH * HW + (size_t)(a * CPA) * HW + hw;

        float logit = (lane < NCLS) ? __ldg(&lb[lane * HW]) : -INFINITY;
        float tv    = (lane < NCLS) ? st[local * CPA + lane] : 0.f;

        // label = position of the single 1.0 in the one-hot
        unsigned lm = __ballot_sync(0xFFFFFFFFu, tv > 0.5f);
        int label = __ffs(lm) - 1;

        // warp max
        float m = logit;
        #pragma unroll
        for (int off = 16; off > 0; off >>= 1)
            m = fmaxf(m, __shfl_xor_sync(0xFFFFFFFFu, m, off));

        // warp sum of exp(logit - m)  (lanes >= 20 contribute 0)
        float ex = __expf(logit - m);
        #pragma unroll
        for (int off = 16; off > 0; off >>= 1)
            ex += __shfl_xor_sync(0xFFFFFFFFu, ex, off);

        float logit_lbl = __shfl_sync(0xFFFFFFFFu, logit, label);
        if (lane == 0)
            cls_l += (m + __logf(ex)) - logit_lbl;   // -logp[label]
    }

    // ---- block reduction of 4 partials (cls_l lives only on lane 0s)
    #pragma unroll
    for (int off = 16; off > 0; off >>= 1) {
        box_l   += __shfl_down_sync(0xFFFFFFFFu, box_l,   off);
        conf_l  += __shfl_down_sync(0xFFFFFFFFu, conf_l,  off);
        noobj_l += __shfl_down_sync(0xFFFFFFFFu, noobj_l, off);
    }

    if (lane == 0) {
        sm[0][wid] = box_l;
        sm[1][wid] = conf_l;
        sm[2][wid] = noobj_l;
        sm[3][wid] = cls_l;
    }
    __syncthreads();
    if (threadIdx.x == 0) {
        float v0 = 0.f, v1 = 0.f, v2 = 0.f, v3 = 0.f;
        #pragma unroll
        for (int w = 0; w < 8; w++) {
            v0 += sm[0][w]; v1 += sm[1][w]; v2 += sm[2][w]; v3 += sm[3][w];
        }
        g_part[blockIdx.x] = make_float4(v0, v1, v2, v3);
        __threadfence();
        unsigned int done = atomicAdd(&g_done, 1u);
        s_last = (done == NBLOCKS - 1);
    }
    __syncthreads();

    // ---- last arriving block: final reduction, direct store, reset counter
    if (s_last) {
        float v0 = 0.f, v1 = 0.f, v2 = 0.f, v3 = 0.f;
        for (int k = threadIdx.x; k < NBLOCKS; k += 256) {
            float4 pp = g_part[k];
            v0 += pp.x; v1 += pp.y; v2 += pp.z; v3 += pp.w;
        }
        #pragma unroll
        for (int off = 16; off > 0; off >>= 1) {
            v0 += __shfl_down_sync(0xFFFFFFFFu, v0, off);
            v1 += __shfl_down_sync(0xFFFFFFFFu, v1, off);
            v2 += __shfl_down_sync(0xFFFFFFFFu, v2, off);
            v3 += __shfl_down_sync(0xFFFFFFFFu, v3, off);
        }
        __syncthreads();   // sm reuse safe
        if (lane == 0) {
            sm[0][wid] = v0; sm[1][wid] = v1; sm[2][wid] = v2; sm[3][wid] = v3;
        }
        __syncthreads();
        if (threadIdx.x == 0) {
            float r0 = 0.f, r1 = 0.f, r2 = 0.f, r3 = 0.f;
            #pragma unroll
            for (int w = 0; w < 8; w++) {
                r0 += sm[0][w]; r1 += sm[1][w]; r2 += sm[2][w]; r3 += sm[3][w];
            }
            const float inv_b = 1.0f / (float)BATCH;
            out[0] = r0 * (5.0f * inv_b);   // LAMBDA_COORD
            out[1] = r1 * (1.0f * inv_b);   // LAMBDA_OBJ
            out[2] = r2 * (0.5f * inv_b);   // LAMBDA_NOOBJ
            out[3] = r3 * (1.0f * inv_b);   // LAMBDA_CLS
            g_done = 0;                     // clean state for next replay
            __threadfence();
        }
    }
}

extern "C" void kernel_launch(void* const* d_in, const int* in_sizes, int n_in,
                              void* d_out, int out_size) {
    const float* pred = (const float*)d_in[0];
    const float* tgt  = (const float*)d_in[1];
    float* out = (float*)d_out;

    yolo_loss_kernel<<<NBLOCKS, 256>>>(pred, tgt, out);   // single graph node
}